// round 1
// baseline (speedup 1.0000x reference)
#include <cuda_runtime.h>
#include <math.h>

#define NN    512
#define FF    128
#define HH    256
#define MM    256
#define DEGN  8
#define HISTN 10
#define OO    64
#define PPV   2
#define MAXS  (10*NN)     /* 5120 */
#define GRID_MAIN 64
#define TPB   256

/* -------- persistent scratch (device globals; no allocation allowed) ------ */
__device__ float g_hist [NN*HISTN*HH];   // node state ring buffers
__device__ float g_keys [NN*HISTN*HH];   // cached keys = state @ Wk + bk
__device__ float g_msgs [MAXS*MM];       // message produced by each step
__device__ float g_wrsum[HH*HH];         // sum of the 4 Wr blocks
__device__ int   g_node [MAXS];          // node consumed at step s
__device__ int   g_prev [MAXS];          // previous step touching same node
__device__ int   g_count[NN];
__device__ int   g_done [MAXS];          // step completion flags

/* ---------------- K1: encode xa -> hist slot0, seed key cache ------------- */
__global__ void k_encode(const float* __restrict__ xa, const float* __restrict__ We,
                         const float* __restrict__ be, const float* __restrict__ Wk,
                         const float* __restrict__ bk)
{
    __shared__ float sx[FF];
    __shared__ float senc[HH];
    int n = blockIdx.x, t = threadIdx.x;
    if (t < FF) sx[t] = xa[n*FF + t];
    __syncthreads();
    float acc = be[t];
    #pragma unroll 4
    for (int f = 0; f < FF; ++f) acc += sx[f] * We[f*HH + t];
    g_hist[((size_t)n*HISTN + 0)*HH + t] = acc;
    senc[t] = acc;
    __syncthreads();
    float k = bk[t];
    #pragma unroll 4
    for (int i = 0; i < HH; ++i) k += senc[i] * Wk[i*HH + t];
    g_keys[((size_t)n*HISTN + 0)*HH + t] = k;
    if (t == 0) g_count[n] = 1;
    if (t < HISTN) g_done[n*HISTN + t] = 0;   // 512*10 == MAXS
}

/* ---------------- K2: Wr_sum = sum of 4 row-blocks of Wr ------------------ */
__global__ void k_wrsum(const float* __restrict__ Wr)
{
    int i = blockIdx.x, t = threadIdx.x;
    g_wrsum[i*HH + t] = Wr[i*HH + t] + Wr[(HH + i)*HH + t]
                      + Wr[(2*HH + i)*HH + t] + Wr[(3*HH + i)*HH + t];
}

/* ------- K3a: node sequence (known prefix grows x8 per round) ------------- */
__global__ void k_seq(const int* __restrict__ neighbors, const int* __restrict__ ns_ptr)
{
    int t = threadIdx.x;
    int S = *ns_ptr;
    for (int e = t; e < S && e < MAXS; e += blockDim.x) g_node[e] = e;
    __syncthreads();
    int known = S;
    while (known < MAXS) {
        long long nx = (long long)S + 8LL*(long long)known;
        int next = (nx > MAXS) ? MAXS : (int)nx;
        for (int e = known + t; e < next; e += blockDim.x) {
            int src = (e - S) >> 3;
            g_node[e] = neighbors[g_node[src]*DEGN + ((e - S) & 7)];
        }
        __syncthreads();
        known = next;
    }
}

/* ------- K3b: prev-same-node links (one thread per node scans seq) -------- */
__global__ void k_prev()
{
    __shared__ int sn[MAXS];   // 20 KB
    int t = threadIdx.x;
    for (int e = t; e < MAXS; e += blockDim.x) sn[e] = g_node[e];
    __syncthreads();
    int mynode = blockIdx.x * blockDim.x + t;
    int last = -1;
    for (int e = 0; e < MAXS; ++e) {
        if (sn[e] == mynode) { g_prev[e] = last; last = e; }
    }
}

/* ---------------- K4: persistent dataflow step processor ------------------ */
__global__ void __launch_bounds__(TPB)
k_main(const float* __restrict__ first_message,
       const float* __restrict__ Wq, const float* __restrict__ bq,
       const float* __restrict__ Wk, const float* __restrict__ bk,
       const float* __restrict__ br,
       const float* __restrict__ Wm, const float* __restrict__ bm,
       const int*   __restrict__ ns_ptr)
{
    __shared__ float s_msg[MM], s_q[HH], s_vals[HH], s_ns[HH];
    __shared__ float s_part[4*HH];
    __shared__ float s_logit[HISTN], s_attn[HISTN];
    __shared__ int   sh_node, sh_cnt;

    const int tid = threadIdx.x;
    const int S   = *ns_ptr;
    const int grp = tid >> 6;      // input-quarter 0..3
    const int c64 = tid & 63;      // output float4 group

    for (int s = blockIdx.x; s < MAXS; s += gridDim.x) {
        const int src = (s >= S) ? ((s - S) >> 3) : -1;

        if (tid == 0) {
            if (src >= 0) { volatile int* f = &g_done[src]; while (*f == 0) {} }
            int pv = g_prev[s];
            if (pv >= 0) { volatile int* f = &g_done[pv]; while (*f == 0) {} }
            __threadfence();                 // acquire
            int nd = g_node[s];
            sh_node = nd;
            sh_cnt  = g_count[nd];
        }
        __syncthreads();
        const int node = sh_node;
        const int cnt  = sh_cnt;
        const int nv   = (cnt < HISTN) ? cnt : HISTN;
        const int slot = cnt % HISTN;

        /* message */
        const float* mp = (src >= 0) ? (g_msgs + (size_t)src*MM)
                                     : (first_message + (size_t)s*MM);
        s_msg[tid] = mp[tid];
        __syncthreads();

        /* query = msg @ Wq + bq */
        {
            const float4* Wv = (const float4*)Wq;
            float a0=0.f,a1=0.f,a2=0.f,a3=0.f;
            const int i0 = grp*64;
            #pragma unroll 8
            for (int i = i0; i < i0+64; ++i) {
                float xv = s_msg[i];
                float4 w = Wv[i*64 + c64];
                a0 += xv*w.x; a1 += xv*w.y; a2 += xv*w.z; a3 += xv*w.w;
            }
            ((float4*)s_part)[grp*64 + c64] = make_float4(a0,a1,a2,a3);
            __syncthreads();
            s_q[tid] = bq[tid] + s_part[tid] + s_part[HH+tid]
                     + s_part[2*HH+tid] + s_part[3*HH+tid];
            __syncthreads();
        }

        /* logits over valid history slots (cached keys) */
        {
            const int w = tid >> 5, l = tid & 31;
            #pragma unroll
            for (int pass = 0; pass < 2; ++pass) {
                int sl = w + pass*8;
                if (sl < nv && sl < HISTN) {
                    const float* kp = g_keys + ((size_t)node*HISTN + sl)*HH;
                    float p = 0.f;
                    #pragma unroll
                    for (int h = l; h < HH; h += 32) p += kp[h]*s_q[h];
                    #pragma unroll
                    for (int o = 16; o > 0; o >>= 1)
                        p += __shfl_down_sync(0xffffffffu, p, o);
                    if (l == 0) s_logit[sl] = p * 0.0625f;   /* 1/sqrt(256) */
                }
            }
        }
        __syncthreads();
        if (tid == 0) {
            float m = -1e30f;
            for (int k = 0; k < nv; ++k) m = fmaxf(m, s_logit[k]);
            float sum = 0.f;
            for (int k = 0; k < nv; ++k) { float e = expf(s_logit[k]-m); s_attn[k]=e; sum+=e; }
            float inv = 1.f / sum;
            for (int k = 0; k < nv; ++k) s_attn[k] *= inv;
        }
        __syncthreads();

        /* values = attn @ hist[node] */
        {
            float v = 0.f;
            const float* hp = g_hist + (size_t)node*HISTN*HH + tid;
            for (int k = 0; k < nv; ++k) v += s_attn[k]*hp[k*HH];
            s_vals[tid] = v;
        }
        __syncthreads();

        /* newstate = vals @ Wr_sum + br ; write to hist ring */
        {
            const float4* Wv = (const float4*)g_wrsum;
            float a0=0.f,a1=0.f,a2=0.f,a3=0.f;
            const int i0 = grp*64;
            #pragma unroll 8
            for (int i = i0; i < i0+64; ++i) {
                float xv = s_vals[i];
                float4 w = Wv[i*64 + c64];
                a0 += xv*w.x; a1 += xv*w.y; a2 += xv*w.z; a3 += xv*w.w;
            }
            ((float4*)s_part)[grp*64 + c64] = make_float4(a0,a1,a2,a3);
            __syncthreads();
            float y = br[tid] + s_part[tid] + s_part[HH+tid]
                    + s_part[2*HH+tid] + s_part[3*HH+tid];
            s_ns[tid] = y;
            g_hist[((size_t)node*HISTN + slot)*HH + tid] = y;
            __syncthreads();
        }

        /* key cache update: keys[node][slot] = ns @ Wk + bk */
        {
            const float4* Wv = (const float4*)Wk;
            float a0=0.f,a1=0.f,a2=0.f,a3=0.f;
            const int i0 = grp*64;
            #pragma unroll 8
            for (int i = i0; i < i0+64; ++i) {
                float xv = s_ns[i];
                float4 w = Wv[i*64 + c64];
                a0 += xv*w.x; a1 += xv*w.y; a2 += xv*w.z; a3 += xv*w.w;
            }
            ((float4*)s_part)[grp*64 + c64] = make_float4(a0,a1,a2,a3);
            __syncthreads();
            g_keys[((size_t)node*HISTN + slot)*HH + tid] =
                bk[tid] + s_part[tid] + s_part[HH+tid]
                        + s_part[2*HH+tid] + s_part[3*HH+tid];
            __syncthreads();
        }

        /* newmessage = [ns,msg] @ Wm + bm  (split: Wm1 rows 0..255, Wm2 rows 256..511) */
        {
            const float4* W1 = (const float4*)Wm;
            const float4* W2 = (const float4*)(Wm + (size_t)HH*MM);
            float a0=0.f,a1=0.f,a2=0.f,a3=0.f;
            const int i0 = grp*64;
            #pragma unroll 4
            for (int i = i0; i < i0+64; ++i) {
                float xv = s_ns[i];
                float4 w = W1[i*64 + c64];
                a0 += xv*w.x; a1 += xv*w.y; a2 += xv*w.z; a3 += xv*w.w;
                float xm = s_msg[i];
                float4 u = W2[i*64 + c64];
                a0 += xm*u.x; a1 += xm*u.y; a2 += xm*u.z; a3 += xm*u.w;
            }
            ((float4*)s_part)[grp*64 + c64] = make_float4(a0,a1,a2,a3);
            __syncthreads();
            g_msgs[(size_t)s*MM + tid] =
                bm[tid] + s_part[tid] + s_part[HH+tid]
                        + s_part[2*HH+tid] + s_part[3*HH+tid];
        }
        __syncthreads();                       /* all gmem writes done */
        if (tid == 0) {
            g_count[node] = cnt + 1;
            __threadfence();                   /* release */
            *(volatile int*)&g_done[s] = 1;
        }
    }
}

/* ---------------- K5: decoder + log_softmax ------------------------------- */
__global__ void k_out(const float* __restrict__ Wd, const float* __restrict__ bd,
                      float* __restrict__ out)
{
    __shared__ float s_fin[HH];
    __shared__ float s_log[PPV*OO];
    int n = blockIdx.x, t = threadIdx.x;     /* 128 threads */
    int cnt  = g_count[n];
    int slot = (cnt - 1) % HISTN;
    s_fin[t]       = g_hist[((size_t)n*HISTN + slot)*HH + t];
    s_fin[t + 128] = g_hist[((size_t)n*HISTN + slot)*HH + t + 128];
    __syncthreads();
    int p = t >> 6, o = t & 63;
    float acc = bd[p*OO + o];
    #pragma unroll 4
    for (int h = 0; h < HH; ++h) acc += s_fin[h]*Wd[((size_t)p*HH + h)*OO + o];
    s_log[t] = acc;
    __syncthreads();
    float m = -1e30f;
    for (int k = 0; k < OO; ++k) m = fmaxf(m, s_log[p*OO + k]);
    float sum = 0.f;
    for (int k = 0; k < OO; ++k) sum += expf(s_log[p*OO + k] - m);
    out[((size_t)p*NN + n)*OO + o] = acc - m - logf(sum);
}

/* -------------------------------------------------------------------------- */
extern "C" void kernel_launch(void* const* d_in, const int* in_sizes, int n_in,
                              void* d_out, int out_size)
{
    const float* xa  = (const float*)d_in[0];
    const int*   nbr = (const int*)  d_in[1];
    const float* fm  = (const float*)d_in[2];
    const float* We  = (const float*)d_in[3];
    const float* be  = (const float*)d_in[4];
    const float* Wq  = (const float*)d_in[5];
    const float* bq  = (const float*)d_in[6];
    const float* Wk  = (const float*)d_in[7];
    const float* bk  = (const float*)d_in[8];
    const float* Wr  = (const float*)d_in[9];
    const float* br  = (const float*)d_in[10];
    const float* Wm  = (const float*)d_in[11];
    const float* bm  = (const float*)d_in[12];
    const float* Wd  = (const float*)d_in[13];
    const float* bd  = (const float*)d_in[14];
    const int*   nS  = (const int*)  d_in[15];   /* small value: int32 read is LE-safe */

    k_encode<<<NN, HH>>>(xa, We, be, Wk, bk);
    k_wrsum <<<HH, HH>>>(Wr);
    k_seq   <<<1, 512>>>(nbr, nS);
    k_prev  <<<8, 64>>>();
    k_main  <<<GRID_MAIN, TPB>>>(fm, Wq, bq, Wk, bk, br, Wm, bm, nS);
    k_out   <<<NN, 128>>>(Wd, bd, (float*)d_out);
}

// round 2
// speedup vs baseline: 4.2507x; 4.2507x over previous
#include <cuda_runtime.h>
#include <math.h>

#define NN    512
#define FF    128
#define HH    256
#define MM    256
#define DEGN  8
#define HISTN 10
#define OO    64
#define PPV   2
#define MAXS  (10*NN)     /* 5120 */
#define GRID_MAIN 148
#define TPB   512

/* -------- persistent scratch (device globals; no allocation allowed) ------ */
__device__ float g_hist [NN*HISTN*HH];   // node state ring buffers
__device__ float g_msgs [MAXS*MM];       // message produced by each step
__device__ float g_wrsum[HH*HH];         // sum of the 4 Wr row-blocks
__device__ float g_wkT  [HH*HH];         // Wk transposed (for kq = Wk @ q)
__device__ int   g_node [MAXS];          // node consumed at step s
__device__ int   g_prev [MAXS];          // previous step touching same node
__device__ int   g_count[NN];
__device__ int   g_done_state[MAXS];     // hist/count published
__device__ int   g_done_msg  [MAXS];     // message published

/* ------------------------- sync helpers ---------------------------------- */
__device__ __forceinline__ int ld_acq(const int* p) {
    int v;
    asm volatile("ld.acquire.gpu.global.b32 %0, [%1];" : "=r"(v) : "l"(p) : "memory");
    return v;
}
__device__ __forceinline__ void st_rel(int* p, int v) {
    asm volatile("st.release.gpu.global.b32 [%0], %1;" :: "l"(p), "r"(v) : "memory");
}

/* ---------------- K1: encode xa -> hist slot0, zero flags ----------------- */
__global__ void k_encode(const float* __restrict__ xa, const float* __restrict__ We,
                         const float* __restrict__ be)
{
    __shared__ float sx[FF];
    int n = blockIdx.x, t = threadIdx.x;
    if (t < FF) sx[t] = xa[n*FF + t];
    __syncthreads();
    float acc = be[t];
    #pragma unroll 4
    for (int f = 0; f < FF; ++f) acc += sx[f] * We[f*HH + t];
    g_hist[((size_t)n*HISTN + 0)*HH + t] = acc;
    if (t == 0) g_count[n] = 1;
    if (t < HISTN) {                       // 512 blocks * 10 == MAXS
        g_done_state[n*HISTN + t] = 0;
        g_done_msg  [n*HISTN + t] = 0;
    }
}

/* ---------------- K2: Wr_sum = sum of 4 row-blocks of Wr ------------------ */
__global__ void k_wrsum(const float* __restrict__ Wr)
{
    int i = blockIdx.x, t = threadIdx.x;
    g_wrsum[i*HH + t] = Wr[i*HH + t] + Wr[(HH + i)*HH + t]
                      + Wr[(2*HH + i)*HH + t] + Wr[(3*HH + i)*HH + t];
}

/* ---------------- K2b: tiled transpose of Wk ------------------------------ */
__global__ void k_wkt(const float* __restrict__ Wk)
{
    __shared__ float tile[32][33];
    int bx = blockIdx.x * 32, by = blockIdx.y * 32;
    int tx = threadIdx.x, ty = threadIdx.y;
    tile[ty][tx] = Wk[(by + ty)*HH + bx + tx];
    __syncthreads();
    g_wkT[(bx + ty)*HH + by + tx] = tile[tx][ty];
}

/* ------- K3: node sequence + prev-same-node links (single block) ---------- */
__global__ void k_graph(const int* __restrict__ neighbors, const int* __restrict__ ns_ptr)
{
    __shared__ int sn[MAXS];   // 20 KB
    int t = threadIdx.x;
    int S = *ns_ptr;
    for (int e = t; e < S && e < MAXS; e += blockDim.x) sn[e] = e;
    __syncthreads();
    int known = S;
    while (known < MAXS) {
        long long nx = (long long)S + 8LL*(long long)known;
        int next = (nx > MAXS) ? MAXS : (int)nx;
        for (int e = known + t; e < next; e += blockDim.x) {
            int src = (e - S) >> 3;
            sn[e] = neighbors[sn[src]*DEGN + ((e - S) & 7)];
        }
        __syncthreads();
        known = next;
    }
    for (int e = t; e < MAXS; e += blockDim.x) g_node[e] = sn[e];
    /* thread t owns node t; every step's node is in [0,NN) so each g_prev[e]
       is written exactly once */
    if (t < NN) {
        int last = -1;
        for (int e = 0; e < MAXS; ++e)
            if (sn[e] == t) { g_prev[e] = last; last = e; }
    }
}

/* ------------- shared split-K matvec: out[256] = xs[256]@W + bias --------- */
__device__ __forceinline__ void matvec256(const float* __restrict__ W,
                                          const float* __restrict__ xs,
                                          const float* __restrict__ bias,
                                          float* __restrict__ out,
                                          float* __restrict__ s_part, int tid)
{
    const int g = tid >> 6, c = tid & 63;
    const float4* Wv = (const float4*)W;
    float a0 = 0.f, a1 = 0.f, a2 = 0.f, a3 = 0.f;
    const int i0 = g * 32;
    #pragma unroll 8
    for (int i = i0; i < i0 + 32; ++i) {
        float x = xs[i];
        float4 w = __ldg(&Wv[i*64 + c]);
        a0 += x*w.x; a1 += x*w.y; a2 += x*w.z; a3 += x*w.w;
    }
    ((float4*)s_part)[g*64 + c] = make_float4(a0, a1, a2, a3);
    __syncthreads();
    if (tid < HH) {
        float r = bias ? bias[tid] : 0.f;
        #pragma unroll
        for (int g2 = 0; g2 < 8; ++g2) r += s_part[g2*HH + tid];
        out[tid] = r;
    }
    __syncthreads();
}

/* ---------------- K4: persistent dataflow step processor ------------------ */
__global__ void __launch_bounds__(TPB)
k_main(const float* __restrict__ first_message,
       const float* __restrict__ Wq, const float* __restrict__ bq,
       const float* __restrict__ br,
       const float* __restrict__ Wm, const float* __restrict__ bm,
       const int*   __restrict__ ns_ptr)
{
    __shared__ float s_msg[MM], s_q[HH], s_kq[HH], s_vals[HH], s_ns[HH];
    __shared__ float s_part[8*HH];
    __shared__ float s_feats[HISTN][HH];
    __shared__ float s_logit[HISTN], s_attn[HISTN];
    __shared__ int   sh_cnt;

    const int tid = threadIdx.x;
    const int S   = *ns_ptr;
    const int wid = tid >> 5, lid = tid & 31;

    for (int s = blockIdx.x; s < MAXS; s += gridDim.x) {
        const int src  = (s >= S) ? ((s - S) >> 3) : -1;
        const int node = g_node[s];
        const int prev = g_prev[s];

        /* ---- Stage A: depends only on source message ---- */
        if (tid == 0 && src >= 0) { while (ld_acq(&g_done_msg[src]) == 0) {} }
        __syncthreads();
        if (tid < MM) {
            const float* mp = (src >= 0) ? (g_msgs + (size_t)src*MM)
                                         : (first_message + (size_t)s*MM);
            s_msg[tid] = __ldcg(mp + tid);
        }
        __syncthreads();
        matvec256(Wq,      s_msg, bq,   s_q,  s_part, tid);   /* q  = msg@Wq+bq */
        matvec256(g_wkT,   s_q,   0,    s_kq, s_part, tid);   /* kq = Wk @ q    */

        /* ---- Stage B: depends on previous visit of this node ---- */
        if (tid == 0) {
            if (prev >= 0) { while (ld_acq(&g_done_state[prev]) == 0) {} }
            sh_cnt = __ldcg(&g_count[node]);
        }
        __syncthreads();
        const int cnt  = sh_cnt;
        const int nv   = (cnt < HISTN) ? cnt : HISTN;
        const int slot = cnt % HISTN;

        /* logits: warp per slot; also stage feats into smem */
        if (wid < nv) {
            const float* hp = g_hist + ((size_t)node*HISTN + wid)*HH;
            float4 f0 = __ldcg((const float4*)(hp) + lid);
            float4 f1 = __ldcg((const float4*)(hp) + 32 + lid);
            ((float4*)s_feats[wid])[lid]      = f0;
            ((float4*)s_feats[wid])[32 + lid] = f1;
            const float4* kq4 = (const float4*)s_kq;
            float4 k0 = kq4[lid], k1 = kq4[32 + lid];
            float p = f0.x*k0.x + f0.y*k0.y + f0.z*k0.z + f0.w*k0.w
                    + f1.x*k1.x + f1.y*k1.y + f1.z*k1.z + f1.w*k1.w;
            #pragma unroll
            for (int o = 16; o > 0; o >>= 1) p += __shfl_down_sync(0xffffffffu, p, o);
            if (lid == 0) s_logit[wid] = p * 0.0625f;   /* 1/sqrt(256) */
        }
        __syncthreads();
        if (tid == 0) {
            float m = -1e30f;
            for (int k = 0; k < nv; ++k) m = fmaxf(m, s_logit[k]);
            float sum = 0.f;
            for (int k = 0; k < nv; ++k) { float e = __expf(s_logit[k]-m); s_attn[k]=e; sum+=e; }
            float inv = 1.f / sum;
            for (int k = 0; k < nv; ++k) s_attn[k] *= inv;
        }
        __syncthreads();

        /* values = attn @ feats (all from smem) */
        if (tid < HH) {
            float v = 0.f;
            #pragma unroll 4
            for (int k = 0; k < nv; ++k) v += s_attn[k] * s_feats[k][tid];
            s_vals[tid] = v;
        }
        __syncthreads();

        /* newstate = vals @ Wr_sum + br ; publish hist + count */
        matvec256(g_wrsum, s_vals, br, s_ns, s_part, tid);
        if (tid < HH) g_hist[((size_t)node*HISTN + slot)*HH + tid] = s_ns[tid];
        if (tid == 0) g_count[node] = cnt + 1;
        __threadfence();
        __syncthreads();
        if (tid == 0) st_rel(&g_done_state[s], 1);

        /* newmessage = [ns,msg] @ Wm + bm  (off the prev-chain) */
        {
            const int g = tid >> 6, c = tid & 63;
            const float4* Wv = (const float4*)Wm;
            const float* xs = (g < 4) ? (s_ns + g*64) : (s_msg + (g-4)*64);
            float a0=0.f,a1=0.f,a2=0.f,a3=0.f;
            const int r0 = g * 64;
            #pragma unroll 8
            for (int i = 0; i < 64; ++i) {
                float x = xs[i];
                float4 w = __ldg(&Wv[(r0+i)*64 + c]);
                a0 += x*w.x; a1 += x*w.y; a2 += x*w.z; a3 += x*w.w;
            }
            ((float4*)s_part)[g*64 + c] = make_float4(a0,a1,a2,a3);
            __syncthreads();
            if (tid < MM) {
                float r = bm[tid];
                #pragma unroll
                for (int g2 = 0; g2 < 8; ++g2) r += s_part[g2*MM + tid];
                g_msgs[(size_t)s*MM + tid] = r;
            }
        }
        __threadfence();
        __syncthreads();
        if (tid == 0) st_rel(&g_done_msg[s], 1);
        __syncthreads();
    }
}

/* ---------------- K5: decoder + log_softmax ------------------------------- */
__global__ void k_out(const float* __restrict__ Wd, const float* __restrict__ bd,
                      float* __restrict__ out)
{
    __shared__ float s_fin[HH];
    __shared__ float s_log[PPV*OO];
    int n = blockIdx.x, t = threadIdx.x;     /* 128 threads */
    int cnt  = g_count[n];
    int slot = (cnt - 1) % HISTN;
    s_fin[t]       = g_hist[((size_t)n*HISTN + slot)*HH + t];
    s_fin[t + 128] = g_hist[((size_t)n*HISTN + slot)*HH + t + 128];
    __syncthreads();
    int p = t >> 6, o = t & 63;
    float acc = bd[p*OO + o];
    #pragma unroll 4
    for (int h = 0; h < HH; ++h) acc += s_fin[h]*Wd[((size_t)p*HH + h)*OO + o];
    s_log[t] = acc;
    __syncthreads();
    float m = -1e30f;
    for (int k = 0; k < OO; ++k) m = fmaxf(m, s_log[p*OO + k]);
    float sum = 0.f;
    for (int k = 0; k < OO; ++k) sum += expf(s_log[p*OO + k] - m);
    out[((size_t)p*NN + n)*OO + o] = acc - m - logf(sum);
}

/* -------------------------------------------------------------------------- */
extern "C" void kernel_launch(void* const* d_in, const int* in_sizes, int n_in,
                              void* d_out, int out_size)
{
    const float* xa  = (const float*)d_in[0];
    const int*   nbr = (const int*)  d_in[1];
    const float* fm  = (const float*)d_in[2];
    const float* We  = (const float*)d_in[3];
    const float* be  = (const float*)d_in[4];
    const float* Wq  = (const float*)d_in[5];
    const float* bq  = (const float*)d_in[6];
    const float* Wk  = (const float*)d_in[7];
    /* d_in[8] = bk  (cancels in softmax; unused) */
    const float* Wr  = (const float*)d_in[9];
    const float* br  = (const float*)d_in[10];
    const float* Wm  = (const float*)d_in[11];
    const float* bm  = (const float*)d_in[12];
    const float* Wd  = (const float*)d_in[13];
    const float* bd  = (const float*)d_in[14];
    const int*   nS  = (const int*)  d_in[15];

    k_encode<<<NN, HH>>>(xa, We, be);
    k_wrsum <<<HH, HH>>>(Wr);
    {
        dim3 g(HH/32, HH/32), b(32, 32);
        k_wkt<<<g, b>>>(Wk);
    }
    k_graph <<<1, 512>>>(nbr, nS);
    k_main  <<<GRID_MAIN, TPB>>>(fm, Wq, bq, br, Wm, bm, nS);
    k_out   <<<NN, 128>>>(Wd, bd, (float*)d_out);
}

// round 3
// speedup vs baseline: 5.6974x; 1.3403x over previous
#include <cuda_runtime.h>
#include <cuda_fp16.h>
#include <math.h>

#define NN    512
#define FF    128
#define HH    256
#define MM    256
#define DEGN  8
#define HISTN 10
#define OO    64
#define PPV   2
#define MAXS  (10*NN)     /* 5120 */
#define NB    148         /* k_main grid */
#define TPB   512
#define CHB   4           /* chunk batch */

/* -------- persistent scratch (device globals; no allocation allowed) ------ */
__device__ float g_hist [NN*HISTN*HH];           // node state ring buffers
__device__ float g_msgs [MAXS*MM];               // message produced by each step
__device__ __align__(16) __half g_A_h [HH*HH];   // A = Wq @ Wk^T (fused q->kq)
__device__ __align__(16) __half g_wr_h[HH*HH];   // fp16 Wr_sum
__device__ __align__(16) __half g_wm_h[2*HH*MM]; // fp16 Wm
__device__ float g_bqk  [HH];                    // Wk @ bq
__device__ int   g_node [MAXS];
__device__ int   g_home [NN];
__device__ int   g_off  [NB+1];
__device__ int   g_steps[MAXS];                  // per-CTA ordered step lists
__device__ int   g_count[NN];
__device__ int   g_done_msg[MAXS];

/* ------------------------- sync helpers ---------------------------------- */
__device__ __forceinline__ int ld_acq(const int* p) {
    int v;
    asm volatile("ld.acquire.gpu.global.b32 %0, [%1];" : "=r"(v) : "l"(p) : "memory");
    return v;
}
__device__ __forceinline__ void st_rel(int* p, int v) {
    asm volatile("st.release.gpu.global.b32 [%0], %1;" :: "l"(p), "r"(v) : "memory");
}

/* ---------------- K1: encode xa -> hist slot0, zero flags ----------------- */
__global__ void k_encode(const float* __restrict__ xa, const float* __restrict__ We,
                         const float* __restrict__ be)
{
    __shared__ float sx[FF];
    int n = blockIdx.x, t = threadIdx.x;
    if (t < FF) sx[t] = xa[n*FF + t];
    __syncthreads();
    float acc = be[t];
    #pragma unroll 4
    for (int f = 0; f < FF; ++f) acc += sx[f] * We[f*HH + t];
    g_hist[((size_t)n*HISTN + 0)*HH + t] = acc;
    if (t < HISTN) g_done_msg[n*HISTN + t] = 0;   // 512*10 == MAXS
}

/* ---------------- K2: Wr_sum (fp16) --------------------------------------- */
__global__ void k_wrsum(const float* __restrict__ Wr)
{
    int i = blockIdx.x, t = threadIdx.x;
    float s = Wr[i*HH + t] + Wr[(HH + i)*HH + t]
            + Wr[(2*HH + i)*HH + t] + Wr[(3*HH + i)*HH + t];
    g_wr_h[i*HH + t] = __float2half(s);
}

/* ---------------- K2b: Wm -> fp16 ----------------------------------------- */
__global__ void k_wmh(const float* __restrict__ Wm)
{
    int b = blockIdx.x, t = threadIdx.x;
    g_wm_h[b*MM + t] = __float2half(Wm[(size_t)b*MM + t]);
}

/* ---------------- K2c: A = Wq @ Wk^T  (fp16 out) -------------------------- */
__global__ void k_prec(const float* __restrict__ Wq, const float* __restrict__ Wk)
{
    __shared__ float a[32][33], bt[32][33];
    int tx = threadIdx.x, ty = threadIdx.y;
    int m0 = blockIdx.y*32, i0 = blockIdx.x*32;
    float acc = 0.f;
    for (int kt = 0; kt < HH; kt += 32) {
        a [ty][tx] = Wq[(m0+ty)*HH + kt + tx];
        bt[tx][ty] = Wk[(i0+ty)*HH + kt + tx];   // bt[h][i]
        __syncthreads();
        #pragma unroll
        for (int k = 0; k < 32; ++k) acc += a[ty][k]*bt[k][tx];
        __syncthreads();
    }
    g_A_h[(m0+ty)*HH + i0 + tx] = __float2half(acc);
}

/* ---------------- K2d: bqk = Wk @ bq -------------------------------------- */
__global__ void k_bqk(const float* __restrict__ Wk, const float* __restrict__ bq)
{
    int w = threadIdx.x >> 5, l = threadIdx.x & 31;
    int r = blockIdx.x*8 + w;
    float p = 0.f;
    #pragma unroll
    for (int k = 0; k < 8; ++k) { int h = l + k*32; p += Wk[r*HH + h]*bq[h]; }
    #pragma unroll
    for (int o = 16; o > 0; o >>= 1) p += __shfl_down_sync(0xffffffffu, p, o);
    if (l == 0) g_bqk[r] = p;
}

/* ------- K3: sequence, visit totals, homes, segment offsets --------------- */
__global__ void k_graph(const int* __restrict__ neighbors, const int* __restrict__ ns_ptr)
{
    __shared__ int sn[MAXS];   // 20 KB
    __shared__ int T[NN], P[NN];
    int t = threadIdx.x;
    int S = *ns_ptr;
    for (int e = t; e < S && e < MAXS; e += TPB) sn[e] = e;
    __syncthreads();
    int known = S;
    while (known < MAXS) {
        long long nx = (long long)S + 8LL*(long long)known;
        int next = (nx > MAXS) ? MAXS : (int)nx;
        for (int e = known + t; e < next; e += TPB) {
            int src = (e - S) >> 3;
            sn[e] = neighbors[sn[src]*DEGN + ((e - S) & 7)];
        }
        __syncthreads();
        known = next;
    }
    T[t] = 0;
    __syncthreads();
    for (int e = t; e < MAXS; e += TPB) atomicAdd(&T[sn[e]], 1);
    __syncthreads();
    P[t] = T[t];
    __syncthreads();
    for (int o = 1; o < NN; o <<= 1) {            // inclusive scan
        int v = (t >= o) ? P[t-o] : 0;
        __syncthreads();
        P[t] += v;
        __syncthreads();
    }
    {
        int excl = P[t] - T[t];
        int h = (int)(((long long)excl * NB) / MAXS);
        g_home[t]  = h;
        g_count[t] = 1 + T[t];
        int hp = (t == 0) ? -1
               : (int)(((long long)(P[t-1] - T[t-1]) * NB) / MAXS);
        for (int c = hp + 1; c <= h; ++c) g_off[c] = excl;
        if (t == NN-1) for (int c = h + 1; c <= NB; ++c) g_off[c] = MAXS;
    }
    for (int e = t; e < MAXS; e += TPB) g_node[e] = sn[e];
}

/* ---------------- K4: persistent home-CTA chunked processor --------------- */
__global__ void __launch_bounds__(TPB)
k_main(const float* __restrict__ first_message,
       const float* __restrict__ br, const float* __restrict__ bm,
       const int*   __restrict__ ns_ptr)
{
    __shared__ float s_msg[CHB][MM];       // 4 KB
    __shared__ float s_kq [CHB][HH];       // 4 KB
    __shared__ float s_ns [CHB][HH];       // 4 KB
    __shared__ float s_vals[HH];           // 1 KB
    __shared__ float s_part[CHB*4*HH];     // 16 KB
    __shared__ float s_logit[16], s_attn[HISTN];
    __shared__ int   s_cnt[NN];            // 2 KB
    __shared__ int   s_scan[TPB];          // 2 KB
    __shared__ int   s_cs[CHB], s_cn[CHB], s_B;

    const int tid = threadIdx.x;
    const int cta = blockIdx.x;
    const int S   = *ns_ptr;
    const int off = g_off[cta];
    const int L   = g_off[cta+1] - off;

    /* ---- build this CTA's ordered step list (stable compaction) ---- */
    {
        int e0 = tid*10, cl = 0;
        #pragma unroll
        for (int k = 0; k < 10; ++k)
            if (g_home[g_node[e0+k]] == cta) ++cl;
        s_scan[tid] = cl;
        __syncthreads();
        for (int o = 1; o < TPB; o <<= 1) {
            int v = (tid >= o) ? s_scan[tid-o] : 0;
            __syncthreads();
            s_scan[tid] += v;
            __syncthreads();
        }
        int base = off + s_scan[tid] - cl;
        #pragma unroll
        for (int k = 0; k < 10; ++k) {
            int e = e0 + k;
            if (g_home[g_node[e]] == cta) g_steps[base++] = e;
        }
        for (int n = tid; n < NN; n += TPB) s_cnt[n] = 1;
        __syncthreads();
    }

    int pos = 0;
    while (pos < L) {
        /* ---- form chunk: block on first msg, opportunistic rest ---- */
        if (tid == 0) {
            int B = 0;
            while (B < CHB && pos + B < L) {
                int s = g_steps[off + pos + B];
                if (s >= S) {
                    int sr = (s - S) >> 3;
                    if (ld_acq(&g_done_msg[sr]) == 0) {
                        if (B == 0) { while (ld_acq(&g_done_msg[sr]) == 0) {} }
                        else break;
                    }
                }
                s_cs[B] = s; s_cn[B] = g_node[s]; ++B;
            }
            s_B = B;
        }
        __syncthreads();
        const int B = s_B;

        /* ---- load chunk messages ---- */
        for (int b = 0; b < B; ++b) {
            if (tid < MM) {
                int s = s_cs[b];
                s_msg[b][tid] = (s < S)
                    ? __ldg(first_message + (size_t)s*MM + tid)
                    : __ldcg(g_msgs + (size_t)((s - S) >> 3)*MM + tid);
            }
        }
        __syncthreads();

        /* ---- batched kq = msg @ A + bqk ---- */
        {
            const int g4 = tid >> 7, c2 = tid & 127;
            const __half2* W = (const __half2*)g_A_h;
            float2 acc[CHB];
            #pragma unroll
            for (int b = 0; b < CHB; ++b) acc[b] = make_float2(0.f, 0.f);
            const int i0 = g4*64;
            #pragma unroll 8
            for (int i = i0; i < i0 + 64; ++i) {
                float2 w = __half22float2(W[i*128 + c2]);
                #pragma unroll
                for (int b = 0; b < CHB; ++b) {
                    float x = s_msg[b][i];
                    acc[b].x += x*w.x; acc[b].y += x*w.y;
                }
            }
            #pragma unroll
            for (int b = 0; b < CHB; ++b)
                ((float2*)s_part)[(b*4 + g4)*128 + c2] = acc[b];
            __syncthreads();
            if (tid < HH) {
                for (int b = 0; b < B; ++b) {
                    float r = g_bqk[tid];
                    #pragma unroll
                    for (int g = 0; g < 4; ++g) r += s_part[(b*4+g)*HH + tid];
                    s_kq[b][tid] = r;
                }
            }
            __syncthreads();
        }

        /* ---- serial per-step: attention + Wr (hist & Wr live in L1) ---- */
        for (int j = 0; j < B; ++j) {
            const int nd   = s_cn[j];
            const int cnt  = s_cnt[nd];
            const int nv   = (cnt < HISTN) ? cnt : HISTN;
            const int slot = cnt % HISTN;
            const int wid = tid >> 5, lid = tid & 31;
            if (wid < nv) {
                const float* hp = g_hist + ((size_t)nd*HISTN + wid)*HH;
                float p = 0.f;
                #pragma unroll
                for (int k = 0; k < 8; ++k) { int h = lid + k*32; p += hp[h]*s_kq[j][h]; }
                #pragma unroll
                for (int o = 16; o > 0; o >>= 1) p += __shfl_down_sync(0xffffffffu, p, o);
                if (lid == 0) s_logit[wid] = p * 0.0625f;
            }
            __syncthreads();
            if (tid == 0) {
                float m = -1e30f;
                for (int k = 0; k < nv; ++k) m = fmaxf(m, s_logit[k]);
                float sum = 0.f;
                for (int k = 0; k < nv; ++k) { float e = __expf(s_logit[k]-m); s_attn[k]=e; sum+=e; }
                float inv = 1.f / sum;
                for (int k = 0; k < nv; ++k) s_attn[k] *= inv;
            }
            __syncthreads();
            if (tid < HH) {
                float v = 0.f;
                const float* hp = g_hist + (size_t)nd*HISTN*HH + tid;
                #pragma unroll 2
                for (int k = 0; k < nv; ++k) v += s_attn[k]*hp[k*HH];
                s_vals[tid] = v;
            }
            __syncthreads();
            {   /* Wr matvec (single vector) */
                const int g4 = tid >> 7, c2 = tid & 127;
                const __half2* W = (const __half2*)g_wr_h;
                float2 acc = make_float2(0.f, 0.f);
                const int i0 = g4*64;
                #pragma unroll 8
                for (int i = i0; i < i0 + 64; ++i) {
                    float2 w = __half22float2(W[i*128 + c2]);
                    float x = s_vals[i];
                    acc.x += x*w.x; acc.y += x*w.y;
                }
                ((float2*)s_part)[g4*128 + c2] = acc;
                __syncthreads();
                if (tid < HH) {
                    float r = __ldg(br + tid);
                    #pragma unroll
                    for (int g = 0; g < 4; ++g) r += s_part[g*HH + tid];
                    s_ns[j][tid] = r;
                    g_hist[((size_t)nd*HISTN + slot)*HH + tid] = r;
                }
                if (tid == TPB-1) s_cnt[nd] = cnt + 1;
                __syncthreads();
            }
        }

        /* ---- batched Wm: [ns,msg] @ Wm + bm -> publish msgs ---- */
        {
            const int g4 = tid >> 7, c2 = tid & 127;
            const __half2* W = (const __half2*)g_wm_h;
            const float* xs[CHB];
            #pragma unroll
            for (int b = 0; b < CHB; ++b)
                xs[b] = (g4 < 2) ? (s_ns[b] + g4*128) : (s_msg[b] + (g4-2)*128);
            float2 acc[CHB];
            #pragma unroll
            for (int b = 0; b < CHB; ++b) acc[b] = make_float2(0.f, 0.f);
            const int i0 = g4*128;
            #pragma unroll 4
            for (int ii = 0; ii < 128; ++ii) {
                float2 w = __half22float2(W[(i0+ii)*128 + c2]);
                #pragma unroll
                for (int b = 0; b < CHB; ++b) {
                    float x = xs[b][ii];
                    acc[b].x += x*w.x; acc[b].y += x*w.y;
                }
            }
            #pragma unroll
            for (int b = 0; b < CHB; ++b)
                ((float2*)s_part)[(b*4 + g4)*128 + c2] = acc[b];
            __syncthreads();
            if (tid < MM) {
                for (int b = 0; b < B; ++b) {
                    float r = __ldg(bm + tid);
                    #pragma unroll
                    for (int g = 0; g < 4; ++g) r += s_part[(b*4+g)*MM + tid];
                    g_msgs[(size_t)s_cs[b]*MM + tid] = r;
                }
            }
            __syncthreads();
            if (tid == 0)
                for (int b = 0; b < B; ++b) st_rel(&g_done_msg[s_cs[b]], 1);
        }
        pos += B;
        __syncthreads();
    }
}

/* ---------------- K5: decoder + log_softmax ------------------------------- */
__global__ void k_out(const float* __restrict__ Wd, const float* __restrict__ bd,
                      float* __restrict__ out)
{
    __shared__ float s_fin[HH];
    __shared__ float s_log[PPV*OO];
    int n = blockIdx.x, t = threadIdx.x;     /* 128 threads */
    int cnt  = g_count[n];
    int slot = (cnt - 1) % HISTN;
    s_fin[t]       = g_hist[((size_t)n*HISTN + slot)*HH + t];
    s_fin[t + 128] = g_hist[((size_t)n*HISTN + slot)*HH + t + 128];
    __syncthreads();
    int p = t >> 6, o = t & 63;
    float acc = bd[p*OO + o];
    #pragma unroll 4
    for (int h = 0; h < HH; ++h) acc += s_fin[h]*Wd[((size_t)p*HH + h)*OO + o];
    s_log[t] = acc;
    __syncthreads();
    float m = -1e30f;
    for (int k = 0; k < OO; ++k) m = fmaxf(m, s_log[p*OO + k]);
    float sum = 0.f;
    for (int k = 0; k < OO; ++k) sum += expf(s_log[p*OO + k] - m);
    out[((size_t)p*NN + n)*OO + o] = acc - m - logf(sum);
}

/* -------------------------------------------------------------------------- */
extern "C" void kernel_launch(void* const* d_in, const int* in_sizes, int n_in,
                              void* d_out, int out_size)
{
    const float* xa  = (const float*)d_in[0];
    const int*   nbr = (const int*)  d_in[1];
    const float* fm  = (const float*)d_in[2];
    const float* We  = (const float*)d_in[3];
    const float* be  = (const float*)d_in[4];
    const float* Wq  = (const float*)d_in[5];
    const float* bq  = (const float*)d_in[6];
    const float* Wk  = (const float*)d_in[7];
    /* d_in[8] = bk cancels in softmax */
    const float* Wr  = (const float*)d_in[9];
    const float* br  = (const float*)d_in[10];
    const float* Wm  = (const float*)d_in[11];
    const float* bm  = (const float*)d_in[12];
    const float* Wd  = (const float*)d_in[13];
    const float* bd  = (const float*)d_in[14];
    const int*   nS  = (const int*)  d_in[15];

    k_encode<<<NN, HH>>>(xa, We, be);
    k_wrsum <<<HH, HH>>>(Wr);
    k_wmh   <<<2*HH, MM>>>(Wm);
    {
        dim3 g(8, 8), b(32, 32);
        k_prec<<<g, b>>>(Wq, Wk);
    }
    k_bqk   <<<8, 256>>>(Wk, bq);
    k_graph <<<1, TPB>>>(nbr, nS);
    k_main  <<<NB, TPB>>>(fm, br, bm, nS);
    k_out   <<<NN, 128>>>(Wd, bd, (float*)d_out);
}